// round 2
// baseline (speedup 1.0000x reference)
#include <cuda_runtime.h>

#define MAXF 8192
#define TILE 256
#define NWARP (TILE/32)
#define JSPLIT 4

// Face data layout (8 floats per face, two float4s):
//   f0 = (nx, ny, nz, q)   with q = 0.5 + |c|^2   (so q_i + q_j = 1 + |ci|^2 + |cj|^2)
//   f1 = (cx, cy, cz, 0)
__device__ __align__(16) float g_srcF[MAXF * 8];
__device__ __align__(16) float g_tarF[MAXF * 8];
__device__ __align__(16) float g_refF[MAXF * 8];
__device__ double g_acc;
__device__ int    g_idx64;   // 1 if index buffers are int64, 0 if int32

// ---------------------------------------------------------------------------
// Detect index dtype: for little-endian int64 values < 2^31, every odd 32-bit
// word is zero. For int32 data those words are random indices — OR != 0.
// ---------------------------------------------------------------------------
__global__ void k_detect(const unsigned int* __restrict__ idx) {
    __shared__ unsigned int s;
    if (threadIdx.x == 0) s = 0u;
    __syncthreads();
    unsigned int v = idx[2 * threadIdx.x + 1];   // words 1,3,...,511 (in-bounds either way)
    atomicOr(&s, v);
    __syncthreads();
    if (threadIdx.x == 0) g_idx64 = (s == 0u) ? 1 : 0;
}

// ---------------------------------------------------------------------------
// Precompute normals/centers from vertices + triangle indices (int32 or int64).
// normal = 0.5 * cross(a-b, c-b); center = (a+b+c)/3
// ---------------------------------------------------------------------------
__global__ void k_faces(const float* __restrict__ v,
                        const void* __restrict__ idxRaw,
                        int which, int nF, int nV) {
    int f = blockIdx.x * blockDim.x + threadIdx.x;
    if (f >= nF) return;
    float* out = which ? g_tarF : g_srcF;

    long long i0, i1, i2;
    if (g_idx64) {
        const long long* idx = (const long long*)idxRaw;
        i0 = idx[3 * f + 0]; i1 = idx[3 * f + 1]; i2 = idx[3 * f + 2];
    } else {
        const int* idx = (const int*)idxRaw;
        i0 = idx[3 * f + 0]; i1 = idx[3 * f + 1]; i2 = idx[3 * f + 2];
    }
    // Safety clamp: never fault, even if dtype detection were wrong.
    if (i0 < 0) i0 = 0; if (i0 >= nV) i0 = nV - 1;
    if (i1 < 0) i1 = 0; if (i1 >= nV) i1 = nV - 1;
    if (i2 < 0) i2 = 0; if (i2 >= nV) i2 = nV - 1;

    float ax = v[3 * i0], ay = v[3 * i0 + 1], az = v[3 * i0 + 2];
    float bx = v[3 * i1], by = v[3 * i1 + 1], bz = v[3 * i1 + 2];
    float cx = v[3 * i2], cy = v[3 * i2 + 1], cz = v[3 * i2 + 2];

    float ux = ax - bx, uy = ay - by, uz = az - bz;
    float wx = cx - bx, wy = cy - by, wz = cz - bz;

    float nx = 0.5f * (uy * wz - uz * wy);
    float ny = 0.5f * (uz * wx - ux * wz);
    float nz = 0.5f * (ux * wy - uy * wx);

    const float third = 1.0f / 3.0f;
    float mx = (ax + bx + cx) * third;
    float my = (ay + by + cy) * third;
    float mz = (az + bz + cz) * third;

    float q = 0.5f + mx * mx + my * my + mz * mz;

    float4* o = (float4*)(out + 8 * f);
    o[0] = make_float4(nx, ny, nz, q);
    o[1] = make_float4(mx, my, mz, 0.0f);
}

__global__ void k_ref(const float* __restrict__ n,
                      const float* __restrict__ c, int nF) {
    int f = blockIdx.x * blockDim.x + threadIdx.x;
    if (f == 0) g_acc = 0.0;   // zero accumulator each launch (deterministic)
    if (f >= nF) return;
    float nx = n[3 * f], ny = n[3 * f + 1], nz = n[3 * f + 2];
    float mx = c[3 * f], my = c[3 * f + 1], mz = c[3 * f + 2];
    float q = 0.5f + mx * mx + my * my + mz * mz;
    float4* o = (float4*)(g_refF + 8 * f);
    o[0] = make_float4(nx, ny, nz, q);
    o[1] = make_float4(mx, my, mz, 0.0f);
}

// ---------------------------------------------------------------------------
// Pairwise energy: one block = 256 rows x jChunk cols of one of 6 pair-blocks.
// Each thread owns one row-face in registers; inner loop walks shared-memory
// column faces (warp-uniform address -> broadcast, conflict-free).
// ---------------------------------------------------------------------------
__global__ void __launch_bounds__(TILE) k_pair(int nS, int nT, int nR, int jChunk) {
    const float *A, *B;
    float w;
    int nRows, nCols;
    switch (blockIdx.y) {
        case 0: A = g_srcF; B = g_srcF; w =  1.8f; nRows = nS; nCols = nS; break;
        case 1: A = g_tarF; B = g_tarF; w =  1.8f; nRows = nT; nCols = nT; break;
        case 2: A = g_refF; B = g_refF; w =  2.0f; nRows = nR; nCols = nR; break;
        case 3: A = g_refF; B = g_srcF; w = -2.0f; nRows = nR; nCols = nS; break;
        case 4: A = g_refF; B = g_tarF; w = -2.0f; nRows = nR; nCols = nT; break;
        default:A = g_tarF; B = g_srcF; w = -1.6f; nRows = nT; nCols = nS; break;
    }

    __shared__ float4 sh[TILE * 2];

    int i = blockIdx.x * TILE + threadIdx.x;
    bool valid = (i < nRows);
    int ic = valid ? i : 0;

    const float4* A4 = (const float4*)A;
    const float4* B4 = (const float4*)B;
    float4 a0 = A4[2 * ic];      // nx ny nz q
    float4 a1 = A4[2 * ic + 1];  // cx cy cz 0

    int j0 = blockIdx.z * jChunk;
    int j1 = min(j0 + jChunk, nCols);

    float acc0 = 0.0f, acc1 = 0.0f;

    for (int jt = j0; jt < j1; jt += TILE) {
        __syncthreads();
        int j = jt + threadIdx.x;
        if (j < nCols) {
            sh[2 * threadIdx.x]     = B4[2 * j];
            sh[2 * threadIdx.x + 1] = B4[2 * j + 1];
        } else {
            // zero normal => contributes 0 regardless of distance
            sh[2 * threadIdx.x]     = make_float4(0.f, 0.f, 0.f, 0.5f);
            sh[2 * threadIdx.x + 1] = make_float4(0.f, 0.f, 0.f, 0.f);
        }
        __syncthreads();

        #pragma unroll 8
        for (int jj = 0; jj < TILE; ++jj) {
            float4 b0 = sh[2 * jj];
            float4 b1 = sh[2 * jj + 1];
            // c_i . c_j
            float cc = fmaf(a1.z, b1.z, fmaf(a1.y, b1.y, a1.x * b1.x));
            // n_i . n_j
            float nn = fmaf(a0.z, b0.z, fmaf(a0.y, b0.y, a0.x * b0.x));
            // u = 1 + |ci|^2 + |cj|^2 - 2 ci.cj = 1 + d
            float u = fmaf(-2.0f, cc, a0.w + b0.w);
            float r;
            asm("rcp.approx.f32 %0, %1;" : "=f"(r) : "f"(u));
            float t = fmaf(nn, r * r, (jj & 1) ? acc1 : acc0);
            if (jj & 1) acc1 = t; else acc0 = t;
        }
    }

    float acc = valid ? (acc0 + acc1) : 0.0f;
    #pragma unroll
    for (int o = 16; o; o >>= 1)
        acc += __shfl_xor_sync(0xffffffffu, acc, o);

    __shared__ float wsum[NWARP];
    int wid = threadIdx.x >> 5;
    if ((threadIdx.x & 31) == 0) wsum[wid] = acc;
    __syncthreads();
    if (threadIdx.x == 0) {
        float s = 0.0f;
        #pragma unroll
        for (int k = 0; k < NWARP; k++) s += wsum[k];
        atomicAdd(&g_acc, (double)(w * s));
    }
}

__global__ void k_out(float* out) { out[0] = (float)g_acc; }

// ---------------------------------------------------------------------------
extern "C" void kernel_launch(void* const* d_in, const int* in_sizes, int n_in,
                              void* d_out, int out_size) {
    const float* sv = (const float*)d_in[0];
    const void*  si = d_in[1];
    const float* tv = (const float*)d_in[2];
    const void*  ti = d_in[3];
    const float* rn = (const float*)d_in[4];
    const float* rc = (const float*)d_in[5];

    int VSn = in_sizes[0] / 3;
    int FSn = in_sizes[1] / 3;
    int VTn = in_sizes[2] / 3;
    int FTn = in_sizes[3] / 3;
    int FRn = in_sizes[4] / 3;

    k_detect<<<1, 256>>>((const unsigned int*)si);
    k_faces<<<(FSn + 255) / 256, 256>>>(sv, si, 0, FSn, VSn);
    k_faces<<<(FTn + 255) / 256, 256>>>(tv, ti, 1, FTn, VTn);
    k_ref  <<<(FRn + 255) / 256, 256>>>(rn, rc, FRn);

    int nMax = FSn > FTn ? FSn : FTn;
    if (FRn > nMax) nMax = FRn;
    int jChunk = (nMax + JSPLIT - 1) / JSPLIT;
    dim3 grid((nMax + TILE - 1) / TILE, 6, JSPLIT);
    k_pair<<<grid, TILE>>>(FSn, FTn, FRn, jChunk);

    k_out<<<1, 1>>>((float*)d_out);
}

// round 3
// speedup vs baseline: 1.3927x; 1.3927x over previous
#include <cuda_runtime.h>

#define MAXF 8192
#define TILE 256
#define NWARP (TILE/32)
#define JSPLIT 8

typedef unsigned long long u64;

// Face data for pair kernel, packed for f32x2 consumption later.
// Row-side (read per-thread): 8 floats/face: [nx ny nz q][cx cy cz 0], q = 0.5+|c|^2
__device__ __align__(16) float g_srcF[MAXF * 8];
__device__ __align__(16) float g_tarF[MAXF * 8];
__device__ __align__(16) float g_refF[MAXF * 8];
__device__ double g_acc;
__device__ unsigned int g_done;

// ---- f32x2 helpers ----------------------------------------------------------
#define F2FMA(d,a,b,c) asm("fma.rn.f32x2 %0, %1, %2, %3;" : "=l"(d) : "l"(a), "l"(b), "l"(c))
#define F2MUL(d,a,b)   asm("mul.rn.f32x2 %0, %1, %2;"     : "=l"(d) : "l"(a), "l"(b))
#define F2ADD(d,a,b)   asm("add.rn.f32x2 %0, %1, %2;"     : "=l"(d) : "l"(a), "l"(b))

__device__ __forceinline__ u64 pk2(float x, float y) {
    u64 r; asm("mov.b64 %0, {%1,%2};" : "=l"(r) : "f"(x), "f"(y)); return r;
}
__device__ __forceinline__ void upk2(float& x, float& y, u64 v) {
    asm("mov.b64 {%0,%1}, %2;" : "=f"(x), "=f"(y) : "l"(v));
}
__device__ __forceinline__ float frcp(float x) {
    float r; asm("rcp.approx.f32 %0, %1;" : "=f"(r) : "f"(x)); return r;
}

// ---------------------------------------------------------------------------
// One fused prep kernel: blockIdx.y = 0 (src faces), 1 (tar faces), 2 (ref).
// Index dtype (int32 vs int64) detected per block from the safe common prefix
// (first 3*nF 32-bit words): little-endian int64 => all odd words are 0.
// ---------------------------------------------------------------------------
__global__ void k_prep(const float* __restrict__ sv, const void* __restrict__ si,
                       int nVS, int nFS,
                       const float* __restrict__ tv, const void* __restrict__ ti,
                       int nVT, int nFT,
                       const float* __restrict__ rn, const float* __restrict__ rc,
                       int nFR) {
    int y = blockIdx.y;
    int f = blockIdx.x * blockDim.x + threadIdx.x;

    if (y == 2) {                            // ref: plain copy + q
        if (f == 0) { g_acc = 0.0; g_done = 0u; }
        if (f >= nFR) return;
        float nx = rn[3*f], ny = rn[3*f+1], nz = rn[3*f+2];
        float mx = rc[3*f], my = rc[3*f+1], mz = rc[3*f+2];
        float q = 0.5f + mx*mx + my*my + mz*mz;
        float4* o = (float4*)(g_refF + 8*f);
        o[0] = make_float4(nx, ny, nz, q);
        o[1] = make_float4(mx, my, mz, 0.0f);
        return;
    }

    const float* v   = y ? tv : sv;
    const void*  idr = y ? ti : si;
    int nV = y ? nVT : nVS;
    int nF = y ? nFT : nFS;
    float* out = y ? g_tarF : g_srcF;

    // ---- dtype detection (all threads participate before any return) ----
    __shared__ unsigned int sOr;
    if (threadIdx.x == 0) sOr = 0u;
    __syncthreads();
    {
        const unsigned int* w = (const unsigned int*)idr;
        int probe = 2 * (int)threadIdx.x + 1;          // odd words of common prefix
        if (probe < 3 * nF) atomicOr(&sOr, w[probe]);
    }
    __syncthreads();
    bool idx64 = (sOr == 0u);

    if (f >= nF) return;

    long long i0, i1, i2;
    if (idx64) {
        const long long* idx = (const long long*)idr;
        i0 = idx[3*f]; i1 = idx[3*f+1]; i2 = idx[3*f+2];
    } else {
        const int* idx = (const int*)idr;
        i0 = idx[3*f]; i1 = idx[3*f+1]; i2 = idx[3*f+2];
    }
    if (i0 < 0) i0 = 0; if (i0 >= nV) i0 = nV - 1;
    if (i1 < 0) i1 = 0; if (i1 >= nV) i1 = nV - 1;
    if (i2 < 0) i2 = 0; if (i2 >= nV) i2 = nV - 1;

    float ax = v[3*i0], ay = v[3*i0+1], az = v[3*i0+2];
    float bx = v[3*i1], by = v[3*i1+1], bz = v[3*i1+2];
    float cx = v[3*i2], cy = v[3*i2+1], cz = v[3*i2+2];

    float ux = ax-bx, uy = ay-by, uz = az-bz;
    float wx = cx-bx, wy = cy-by, wz = cz-bz;

    float nx = 0.5f*(uy*wz - uz*wy);
    float ny = 0.5f*(uz*wx - ux*wz);
    float nz = 0.5f*(ux*wy - uy*wx);

    const float third = 1.0f/3.0f;
    float mx = (ax+bx+cx)*third, my = (ay+by+cy)*third, mz = (az+bz+cz)*third;
    float q = 0.5f + mx*mx + my*my + mz*mz;

    float4* o = (float4*)(out + 8*f);
    o[0] = make_float4(nx, ny, nz, q);
    o[1] = make_float4(mx, my, mz, 0.0f);
}

// ---------------------------------------------------------------------------
// Pairwise energy, f32x2 math: each thread owns one row-face (components
// duplicated into both f32x2 halves); inner loop walks 2 column-faces at a
// time from shared memory (components of j and j+1 packed into one f32x2).
// Shared stores cs = -2*c so u = qi + qj - 2 ci.cj is a pure fma chain.
// ---------------------------------------------------------------------------
__global__ void __launch_bounds__(TILE) k_pair(int nS, int nT, int nR, int jChunk,
                                               float* __restrict__ outp) {
    const float *A, *B;
    float w;
    int nRows, nCols;
    switch (blockIdx.y) {
        case 0: A = g_srcF; B = g_srcF; w =  1.8f; nRows = nS; nCols = nS; break;
        case 1: A = g_tarF; B = g_tarF; w =  1.8f; nRows = nT; nCols = nT; break;
        case 2: A = g_refF; B = g_refF; w =  2.0f; nRows = nR; nCols = nR; break;
        case 3: A = g_refF; B = g_srcF; w = -2.0f; nRows = nR; nCols = nS; break;
        case 4: A = g_refF; B = g_tarF; w = -2.0f; nRows = nR; nCols = nT; break;
        default:A = g_tarF; B = g_srcF; w = -1.6f; nRows = nT; nCols = nS; break;
    }

    // 128 j-pairs x 8 u64 slots: [nx2 ny2 nz2 q2 csx2 csy2 csz2 pad] = 8 KB
    __shared__ __align__(16) u64 sh[(TILE/2) * 8];
    float* shf = (float*)sh;

    int i = blockIdx.x * TILE + threadIdx.x;
    bool valid = (i < nRows);
    int ic = valid ? i : 0;

    const float4* A4 = (const float4*)A;
    const float4* B4 = (const float4*)B;
    float4 a0 = A4[2*ic];      // nx ny nz q
    float4 a1 = A4[2*ic+1];    // cx cy cz 0

    u64 anx2 = pk2(a0.x, a0.x), any2 = pk2(a0.y, a0.y), anz2 = pk2(a0.z, a0.z);
    u64 acx2 = pk2(a1.x, a1.x), acy2 = pk2(a1.y, a1.y), acz2 = pk2(a1.z, a1.z);
    u64 aq2  = pk2(a0.w, a0.w);

    int j0 = blockIdx.z * jChunk;
    int j1 = min(j0 + jChunk, nCols);

    u64 accA = 0ull, accB = 0ull;   // f32x2 zero pairs

    for (int jt = j0; jt < j1; jt += TILE) {
        __syncthreads();
        {
            int t = threadIdx.x;
            int j = jt + t;
            int p = t >> 1, h = t & 1;
            float nx, ny, nz, q, cx, cy, cz;
            if (j < nCols) {
                float4 b0 = B4[2*j];
                float4 b1 = B4[2*j+1];
                nx = b0.x; ny = b0.y; nz = b0.z; q = b0.w;
                cx = -2.0f*b1.x; cy = -2.0f*b1.y; cz = -2.0f*b1.z;
            } else {
                nx = ny = nz = 0.0f; q = 0.5f; cx = cy = cz = 0.0f;
            }
            float* d = shf + p*16 + h;
            d[0] = nx; d[2] = ny; d[4] = nz; d[6] = q;
            d[8] = cx; d[10] = cy; d[12] = cz;
        }
        __syncthreads();

        const ulonglong2* shv = (const ulonglong2*)sh;
        #pragma unroll 8
        for (int p = 0; p < TILE/2; ++p) {
            ulonglong2 v0 = shv[p*4 + 0];   // nx2 ny2
            ulonglong2 v1 = shv[p*4 + 1];   // nz2 q2
            ulonglong2 v2 = shv[p*4 + 2];   // csx2 csy2
            ulonglong2 v3 = shv[p*4 + 3];   // csz2 pad

            u64 nn2, u2, rr2;
            F2MUL(nn2, anx2, v0.x);
            F2FMA(nn2, any2, v0.y, nn2);
            F2FMA(nn2, anz2, v1.x, nn2);

            F2FMA(u2, acx2, v2.x, v1.y);    // qj - 2cx*cjx
            F2FMA(u2, acy2, v2.y, u2);
            F2FMA(u2, acz2, v3.x, u2);
            F2ADD(u2, u2, aq2);             // + qi  => 1 + |ci-cj|^2

            float ua, ub; upk2(ua, ub, u2);
            u64 r2 = pk2(frcp(ua), frcp(ub));
            F2MUL(rr2, r2, r2);
            if (p & 1) { F2FMA(accB, nn2, rr2, accB); }
            else       { F2FMA(accA, nn2, rr2, accA); }
        }
    }

    float a_, b_, c_, d_;
    upk2(a_, b_, accA); upk2(c_, d_, accB);
    float acc = valid ? ((a_ + b_) + (c_ + d_)) : 0.0f;

    #pragma unroll
    for (int o = 16; o; o >>= 1)
        acc += __shfl_xor_sync(0xffffffffu, acc, o);

    __shared__ float wsum[NWARP];
    int wid = threadIdx.x >> 5;
    if ((threadIdx.x & 31) == 0) wsum[wid] = acc;
    __syncthreads();
    if (threadIdx.x == 0) {
        float s = 0.0f;
        #pragma unroll
        for (int k = 0; k < NWARP; k++) s += wsum[k];
        atomicAdd(&g_acc, (double)(w * s));
        __threadfence();
        unsigned int total = gridDim.x * gridDim.y * gridDim.z;
        unsigned int ticket = atomicAdd(&g_done, 1u);
        if (ticket == total - 1u) outp[0] = (float)g_acc;   // last block writes out
    }
}

// ---------------------------------------------------------------------------
extern "C" void kernel_launch(void* const* d_in, const int* in_sizes, int n_in,
                              void* d_out, int out_size) {
    const float* sv = (const float*)d_in[0];
    const void*  si = d_in[1];
    const float* tv = (const float*)d_in[2];
    const void*  ti = d_in[3];
    const float* rn = (const float*)d_in[4];
    const float* rc = (const float*)d_in[5];

    int VSn = in_sizes[0] / 3;
    int FSn = in_sizes[1] / 3;
    int VTn = in_sizes[2] / 3;
    int FTn = in_sizes[3] / 3;
    int FRn = in_sizes[4] / 3;

    int nMax = FSn > FTn ? FSn : FTn;
    if (FRn > nMax) nMax = FRn;

    dim3 pgrid((nMax + 255) / 256, 3, 1);
    k_prep<<<pgrid, 256>>>(sv, si, VSn, FSn, tv, ti, VTn, FTn, rn, rc, FRn);

    // jChunk must be a multiple of TILE (inner tile loop assumes aligned chunks)
    int nTilesJ = (nMax + TILE - 1) / TILE;
    int tPerChunk = (nTilesJ + JSPLIT - 1) / JSPLIT;
    int jChunk = tPerChunk * TILE;
    int zSplit = (nTilesJ + tPerChunk - 1) / tPerChunk;

    dim3 grid((nMax + TILE - 1) / TILE, 6, zSplit);
    k_pair<<<grid, TILE>>>(FSn, FTn, FRn, jChunk, (float*)d_out);
}

// round 4
// speedup vs baseline: 1.6501x; 1.1848x over previous
#include <cuda_runtime.h>

#define MAXF 8192
#define NT   256          // threads per block
#define TJ   256          // j columns per shared tile
#define RPB  512          // rows per block (2 per thread)
#define NWARP (NT/32)
#define JSPLIT 8

typedef unsigned long long u64;

// Face data: 8 floats/face: [nx ny nz q][cx cy cz 0], q = 0.5 + |c|^2
__device__ __align__(16) float g_srcF[MAXF * 8];
__device__ __align__(16) float g_tarF[MAXF * 8];
__device__ __align__(16) float g_refF[MAXF * 8];
__device__ double g_acc;
__device__ unsigned int g_done;

// ---- f32x2 helpers ----------------------------------------------------------
#define F2FMA(d,a,b,c) asm("fma.rn.f32x2 %0, %1, %2, %3;" : "=l"(d) : "l"(a), "l"(b), "l"(c))
#define F2MUL(d,a,b)   asm("mul.rn.f32x2 %0, %1, %2;"     : "=l"(d) : "l"(a), "l"(b))
#define F2ADD(d,a,b)   asm("add.rn.f32x2 %0, %1, %2;"     : "=l"(d) : "l"(a), "l"(b))

__device__ __forceinline__ u64 pk2(float x, float y) {
    u64 r; asm("mov.b64 %0, {%1,%2};" : "=l"(r) : "f"(x), "f"(y)); return r;
}
__device__ __forceinline__ void upk2(float& x, float& y, u64 v) {
    asm("mov.b64 {%0,%1}, %2;" : "=f"(x), "=f"(y) : "l"(v));
}
__device__ __forceinline__ float frcp(float x) {
    float r; asm("rcp.approx.f32 %0, %1;" : "=f"(r) : "f"(x)); return r;
}

// ---------------------------------------------------------------------------
// Fused prep: blockIdx.y = 0 (src faces), 1 (tar faces), 2 (ref copy).
// Index dtype detected per block: little-endian int64 => all odd words zero.
// ---------------------------------------------------------------------------
__global__ void k_prep(const float* __restrict__ sv, const void* __restrict__ si,
                       int nVS, int nFS,
                       const float* __restrict__ tv, const void* __restrict__ ti,
                       int nVT, int nFT,
                       const float* __restrict__ rn, const float* __restrict__ rc,
                       int nFR) {
    int y = blockIdx.y;
    int f = blockIdx.x * blockDim.x + threadIdx.x;

    if (y == 2) {
        if (f == 0) { g_acc = 0.0; g_done = 0u; }
        if (f >= nFR) return;
        float nx = rn[3*f], ny = rn[3*f+1], nz = rn[3*f+2];
        float mx = rc[3*f], my = rc[3*f+1], mz = rc[3*f+2];
        float q = 0.5f + mx*mx + my*my + mz*mz;
        float4* o = (float4*)(g_refF + 8*f);
        o[0] = make_float4(nx, ny, nz, q);
        o[1] = make_float4(mx, my, mz, 0.0f);
        return;
    }

    const float* v   = y ? tv : sv;
    const void*  idr = y ? ti : si;
    int nV = y ? nVT : nVS;
    int nF = y ? nFT : nFS;
    float* out = y ? g_tarF : g_srcF;

    __shared__ unsigned int sOr;
    if (threadIdx.x == 0) sOr = 0u;
    __syncthreads();
    {
        const unsigned int* w = (const unsigned int*)idr;
        int probe = 2 * (int)threadIdx.x + 1;
        if (probe < 3 * nF) atomicOr(&sOr, w[probe]);
    }
    __syncthreads();
    bool idx64 = (sOr == 0u);

    if (f >= nF) return;

    long long i0, i1, i2;
    if (idx64) {
        const long long* idx = (const long long*)idr;
        i0 = idx[3*f]; i1 = idx[3*f+1]; i2 = idx[3*f+2];
    } else {
        const int* idx = (const int*)idr;
        i0 = idx[3*f]; i1 = idx[3*f+1]; i2 = idx[3*f+2];
    }
    if (i0 < 0) i0 = 0; if (i0 >= nV) i0 = nV - 1;
    if (i1 < 0) i1 = 0; if (i1 >= nV) i1 = nV - 1;
    if (i2 < 0) i2 = 0; if (i2 >= nV) i2 = nV - 1;

    float ax = v[3*i0], ay = v[3*i0+1], az = v[3*i0+2];
    float bx = v[3*i1], by = v[3*i1+1], bz = v[3*i1+2];
    float cx = v[3*i2], cy = v[3*i2+1], cz = v[3*i2+2];

    float ux = ax-bx, uy = ay-by, uz = az-bz;
    float wx = cx-bx, wy = cy-by, wz = cz-bz;

    float nx = 0.5f*(uy*wz - uz*wy);
    float ny = 0.5f*(uz*wx - ux*wz);
    float nz = 0.5f*(ux*wy - uy*wx);

    const float third = 1.0f/3.0f;
    float mx = (ax+bx+cx)*third, my = (ay+by+cy)*third, mz = (az+bz+cz)*third;
    float q = 0.5f + mx*mx + my*my + mz*mz;

    float4* o = (float4*)(out + 8*f);
    o[0] = make_float4(nx, ny, nz, q);
    o[1] = make_float4(mx, my, mz, 0.0f);
}

// ---------------------------------------------------------------------------
// Pair kernel: 2 rows/thread (r, r+256), j-pairs packed in f32x2 halves in
// shared memory. Symmetric blocks (y<3) process only j-tiles >= row subtile;
// diagonal tile weight 1, above-diagonal weight 2 (mirror covered).
// ---------------------------------------------------------------------------
__global__ void __launch_bounds__(NT) k_pair(int nS, int nT, int nR,
                                             float* __restrict__ outp) {
    const float *A, *B;
    float w;
    int nRows, nCols;
    switch (blockIdx.y) {
        case 0: A = g_srcF; B = g_srcF; w =  1.8f; nRows = nS; nCols = nS; break;
        case 1: A = g_tarF; B = g_tarF; w =  1.8f; nRows = nT; nCols = nT; break;
        case 2: A = g_refF; B = g_refF; w =  2.0f; nRows = nR; nCols = nR; break;
        case 3: A = g_refF; B = g_srcF; w = -2.0f; nRows = nR; nCols = nS; break;
        case 4: A = g_refF; B = g_tarF; w = -2.0f; nRows = nR; nCols = nT; break;
        default:A = g_tarF; B = g_srcF; w = -1.6f; nRows = nT; nCols = nS; break;
    }
    bool sym = (blockIdx.y < 3);

    // 128 j-pairs x 8 u64: [nx2 ny2 nz2 q2 csx2 csy2 csz2 pad] = 8 KB
    __shared__ __align__(16) u64 sh[(TJ/2) * 8];
    float* shf = (float*)sh;

    const float4* A4 = (const float4*)A;
    const float4* B4 = (const float4*)B;

    // Row data (2 rows per thread), duplicated into both f32x2 halves.
    int r0 = blockIdx.x * RPB + threadIdx.x;
    int r1 = r0 + TJ;
    u64 nR0[3], cR0[3], qR0, nR1[3], cR1[3], qR1;
    {
        float4 a0, a1;
        if (r0 < nRows) { a0 = A4[2*r0]; a1 = A4[2*r0+1]; }
        else { a0 = make_float4(0,0,0,0.5f); a1 = make_float4(0,0,0,0); }
        nR0[0]=pk2(a0.x,a0.x); nR0[1]=pk2(a0.y,a0.y); nR0[2]=pk2(a0.z,a0.z);
        cR0[0]=pk2(a1.x,a1.x); cR0[1]=pk2(a1.y,a1.y); cR0[2]=pk2(a1.z,a1.z);
        qR0 = pk2(a0.w,a0.w);
        if (r1 < nRows) { a0 = A4[2*r1]; a1 = A4[2*r1+1]; }
        else { a0 = make_float4(0,0,0,0.5f); a1 = make_float4(0,0,0,0); }
        nR1[0]=pk2(a0.x,a0.x); nR1[1]=pk2(a0.y,a0.y); nR1[2]=pk2(a0.z,a0.z);
        cR1[0]=pk2(a1.x,a1.x); cR1[1]=pk2(a1.y,a1.y); cR1[2]=pk2(a1.z,a1.z);
        qR1 = pk2(a0.w,a0.w);
    }

    int nTilesJ = (nCols + TJ - 1) / TJ;
    int s0 = 2 * blockIdx.x;          // row-subtile index of rows [r0 base, +256)
    int s1 = s0 + 1;                  // row-subtile of rows [+256, +512)

    int tiles0 = sym ? (s0 < nTilesJ ? s0 : nTilesJ) : 0;
    int cnt = nTilesJ - tiles0;
    int per = (cnt + (int)gridDim.z - 1) / (int)gridDim.z;
    int t0 = tiles0 + (int)blockIdx.z * per;
    int t1 = t0 + per; if (t1 > nTilesJ) t1 = nTilesJ;

    u64 acc0 = 0ull, acc1 = 0ull;

    for (int tj = t0; tj < t1; ++tj) {
        int jt = tj * TJ;
        __syncthreads();
        {
            int t = threadIdx.x;
            int j = jt + t;
            int p = t >> 1, h = t & 1;
            float nx, ny, nz, q, cx, cy, cz;
            if (j < nCols) {
                float4 b0 = B4[2*j];
                float4 b1 = B4[2*j+1];
                nx = b0.x; ny = b0.y; nz = b0.z; q = b0.w;
                cx = -2.0f*b1.x; cy = -2.0f*b1.y; cz = -2.0f*b1.z;
            } else {
                nx = ny = nz = 0.0f; q = 0.5f; cx = cy = cz = 0.0f;
            }
            float* d = shf + p*16 + h;
            d[0] = nx; d[2] = ny; d[4] = nz; d[6] = q;
            d[8] = cx; d[10] = cy; d[12] = cz;
        }
        __syncthreads();

        u64 aT0 = 0ull, aT1 = 0ull;
        const ulonglong2* shv = (const ulonglong2*)sh;
        #pragma unroll 4
        for (int p = 0; p < TJ/2; ++p) {
            ulonglong2 v0 = shv[p*4 + 0];   // nx2 ny2
            ulonglong2 v1 = shv[p*4 + 1];   // nz2 q2
            ulonglong2 v2 = shv[p*4 + 2];   // csx2 csy2
            ulonglong2 v3 = shv[p*4 + 3];   // csz2 pad

            // row 0
            {
                u64 nn, u, rr;
                F2MUL(nn, nR0[0], v0.x);
                F2FMA(nn, nR0[1], v0.y, nn);
                F2FMA(nn, nR0[2], v1.x, nn);
                F2FMA(u, cR0[0], v2.x, v1.y);
                F2FMA(u, cR0[1], v2.y, u);
                F2FMA(u, cR0[2], v3.x, u);
                F2ADD(u, u, qR0);
                float ua, ub; upk2(ua, ub, u);
                u64 r2 = pk2(frcp(ua), frcp(ub));
                F2MUL(rr, r2, r2);
                F2FMA(aT0, nn, rr, aT0);
            }
            // row 1
            {
                u64 nn, u, rr;
                F2MUL(nn, nR1[0], v0.x);
                F2FMA(nn, nR1[1], v0.y, nn);
                F2FMA(nn, nR1[2], v1.x, nn);
                F2FMA(u, cR1[0], v2.x, v1.y);
                F2FMA(u, cR1[1], v2.y, u);
                F2FMA(u, cR1[2], v3.x, u);
                F2ADD(u, u, qR1);
                float ua, ub; upk2(ua, ub, u);
                u64 r2 = pk2(frcp(ua), frcp(ub));
                F2MUL(rr, r2, r2);
                F2FMA(aT1, nn, rr, aT1);
            }
        }

        float w0f, w1f;
        if (sym) {
            w0f = (tj == s0) ? 1.0f : 2.0f;                       // tj >= s0 always
            w1f = (tj < s1) ? 0.0f : ((tj == s1) ? 1.0f : 2.0f);
        } else {
            w0f = 1.0f; w1f = 1.0f;
        }
        u64 w02 = pk2(w0f, w0f), w12 = pk2(w1f, w1f);
        F2FMA(acc0, w02, aT0, acc0);
        F2FMA(acc1, w12, aT1, acc1);
    }

    float a_, b_, c_, d_;
    upk2(a_, b_, acc0); upk2(c_, d_, acc1);
    float acc = w * ((a_ + b_) + (c_ + d_));

    #pragma unroll
    for (int o = 16; o; o >>= 1)
        acc += __shfl_xor_sync(0xffffffffu, acc, o);

    __shared__ float wsum[NWARP];
    int wid = threadIdx.x >> 5;
    if ((threadIdx.x & 31) == 0) wsum[wid] = acc;
    __syncthreads();
    if (threadIdx.x == 0) {
        float s = 0.0f;
        #pragma unroll
        for (int k = 0; k < NWARP; k++) s += wsum[k];
        atomicAdd(&g_acc, (double)s);
        __threadfence();
        unsigned int total = gridDim.x * gridDim.y * gridDim.z;
        unsigned int ticket = atomicAdd(&g_done, 1u);
        if (ticket == total - 1u) outp[0] = (float)g_acc;
    }
}

// ---------------------------------------------------------------------------
extern "C" void kernel_launch(void* const* d_in, const int* in_sizes, int n_in,
                              void* d_out, int out_size) {
    const float* sv = (const float*)d_in[0];
    const void*  si = d_in[1];
    const float* tv = (const float*)d_in[2];
    const void*  ti = d_in[3];
    const float* rn = (const float*)d_in[4];
    const float* rc = (const float*)d_in[5];

    int VSn = in_sizes[0] / 3;
    int FSn = in_sizes[1] / 3;
    int VTn = in_sizes[2] / 3;
    int FTn = in_sizes[3] / 3;
    int FRn = in_sizes[4] / 3;

    int nMax = FSn > FTn ? FSn : FTn;
    if (FRn > nMax) nMax = FRn;

    dim3 pgrid((nMax + 255) / 256, 3, 1);
    k_prep<<<pgrid, 256>>>(sv, si, VSn, FSn, tv, ti, VTn, FTn, rn, rc, FRn);

    int gx = (nMax + RPB - 1) / RPB;
    dim3 grid(gx, 6, JSPLIT);
    k_pair<<<grid, NT>>>(FSn, FTn, FRn, (float*)d_out);
}

// round 5
// speedup vs baseline: 2.0732x; 1.2564x over previous
#include <cuda_runtime.h>

#define MAXF 8192
#define NT   256          // threads per block
#define TJ   256          // j columns per shared tile
#define RPB  512          // rows per block (2 per thread)
#define NWARP (NT/32)

typedef unsigned long long u64;

// Face data: 8 floats/face: [nx ny nz q][cx cy cz 0], q = 0.5 + |c|^2
__device__ __align__(16) float g_srcF[MAXF * 8];
__device__ __align__(16) float g_tarF[MAXF * 8];
__device__ __align__(16) float g_refF[MAXF * 8];
__device__ double g_acc;
__device__ unsigned int g_done;

// ---- f32x2 helpers ----------------------------------------------------------
#define F2FMA(d,a,b,c) asm("fma.rn.f32x2 %0, %1, %2, %3;" : "=l"(d) : "l"(a), "l"(b), "l"(c))
#define F2MUL(d,a,b)   asm("mul.rn.f32x2 %0, %1, %2;"     : "=l"(d) : "l"(a), "l"(b))
#define F2ADD(d,a,b)   asm("add.rn.f32x2 %0, %1, %2;"     : "=l"(d) : "l"(a), "l"(b))

__device__ __forceinline__ u64 pk2(float x, float y) {
    u64 r; asm("mov.b64 %0, {%1,%2};" : "=l"(r) : "f"(x), "f"(y)); return r;
}
__device__ __forceinline__ void upk2(float& x, float& y, u64 v) {
    asm("mov.b64 {%0,%1}, %2;" : "=f"(x), "=f"(y) : "l"(v));
}
__device__ __forceinline__ float frcp(float x) {
    float r; asm("rcp.approx.f32 %0, %1;" : "=f"(r) : "f"(x)); return r;
}

// ---------------------------------------------------------------------------
// Fused prep: blockIdx.y = 0 (src faces), 1 (tar faces), 2 (ref copy).
// Index dtype detected per block: little-endian int64 => all odd words zero.
// ---------------------------------------------------------------------------
__global__ void k_prep(const float* __restrict__ sv, const void* __restrict__ si,
                       int nVS, int nFS,
                       const float* __restrict__ tv, const void* __restrict__ ti,
                       int nVT, int nFT,
                       const float* __restrict__ rn, const float* __restrict__ rc,
                       int nFR) {
    int y = blockIdx.y;
    int f = blockIdx.x * blockDim.x + threadIdx.x;

    if (y == 2) {
        if (f == 0) { g_acc = 0.0; g_done = 0u; }
        if (f >= nFR) return;
        float nx = rn[3*f], ny = rn[3*f+1], nz = rn[3*f+2];
        float mx = rc[3*f], my = rc[3*f+1], mz = rc[3*f+2];
        float q = 0.5f + mx*mx + my*my + mz*mz;
        float4* o = (float4*)(g_refF + 8*f);
        o[0] = make_float4(nx, ny, nz, q);
        o[1] = make_float4(mx, my, mz, 0.0f);
        return;
    }

    const float* v   = y ? tv : sv;
    const void*  idr = y ? ti : si;
    int nV = y ? nVT : nVS;
    int nF = y ? nFT : nFS;
    float* out = y ? g_tarF : g_srcF;

    __shared__ unsigned int sOr;
    if (threadIdx.x == 0) sOr = 0u;
    __syncthreads();
    {
        const unsigned int* w = (const unsigned int*)idr;
        int probe = 2 * (int)threadIdx.x + 1;
        if (probe < 3 * nF) atomicOr(&sOr, w[probe]);
    }
    __syncthreads();
    bool idx64 = (sOr == 0u);

    if (f >= nF) return;

    long long i0, i1, i2;
    if (idx64) {
        const long long* idx = (const long long*)idr;
        i0 = idx[3*f]; i1 = idx[3*f+1]; i2 = idx[3*f+2];
    } else {
        const int* idx = (const int*)idr;
        i0 = idx[3*f]; i1 = idx[3*f+1]; i2 = idx[3*f+2];
    }
    if (i0 < 0) i0 = 0; if (i0 >= nV) i0 = nV - 1;
    if (i1 < 0) i1 = 0; if (i1 >= nV) i1 = nV - 1;
    if (i2 < 0) i2 = 0; if (i2 >= nV) i2 = nV - 1;

    float ax = v[3*i0], ay = v[3*i0+1], az = v[3*i0+2];
    float bx = v[3*i1], by = v[3*i1+1], bz = v[3*i1+2];
    float cx = v[3*i2], cy = v[3*i2+1], cz = v[3*i2+2];

    float ux = ax-bx, uy = ay-by, uz = az-bz;
    float wx = cx-bx, wy = cy-by, wz = cz-bz;

    float nx = 0.5f*(uy*wz - uz*wy);
    float ny = 0.5f*(uz*wx - ux*wz);
    float nz = 0.5f*(ux*wy - uy*wx);

    const float third = 1.0f/3.0f;
    float mx = (ax+bx+cx)*third, my = (ay+by+cy)*third, mz = (az+bz+cz)*third;
    float q = 0.5f + mx*mx + my*my + mz*mz;

    float4* o = (float4*)(out + 8*f);
    o[0] = make_float4(nx, ny, nz, q);
    o[1] = make_float4(mx, my, mz, 0.0f);
}

// ---------------------------------------------------------------------------
// Pair kernel, flattened uniform work units: one CTA = one 512x256 tile.
// Region decode via prefix offsets; symmetric regions enumerate only j-tiles
// >= row subtile (triangular), weights 1 on diagonal subtile, 2 above.
// ---------------------------------------------------------------------------
__global__ void __launch_bounds__(NT) k_pair(int nS, int nT, int nR,
                                             int o1, int o2, int o3, int o4, int o5,
                                             int total,
                                             float* __restrict__ outp) {
    int b = blockIdx.x;
    int region = (b >= o3) ? ((b >= o5) ? 5 : (b >= o4) ? 4 : 3)
                           : ((b >= o2) ? 2 : (b >= o1) ? 1 : 0);
    int local;
    const float *A, *B;
    float w;
    int nRows, nCols;
    switch (region) {
        case 0: A=g_srcF; B=g_srcF; w= 1.8f; nRows=nS; nCols=nS; local=b;      break;
        case 1: A=g_tarF; B=g_tarF; w= 1.8f; nRows=nT; nCols=nT; local=b-o1;   break;
        case 2: A=g_refF; B=g_refF; w= 2.0f; nRows=nR; nCols=nR; local=b-o2;   break;
        case 3: A=g_refF; B=g_srcF; w=-2.0f; nRows=nR; nCols=nS; local=b-o3;   break;
        case 4: A=g_refF; B=g_tarF; w=-2.0f; nRows=nR; nCols=nT; local=b-o4;   break;
        default:A=g_tarF; B=g_srcF; w=-1.6f; nRows=nT; nCols=nS; local=b-o5;   break;
    }
    bool sym = (region < 3);

    int J = (nCols + TJ - 1) / TJ;          // j-tiles
    int Rb = (nRows + RPB - 1) / RPB;       // row-blocks

    int s2, tj;                              // row-block, j-tile indices
    if (sym) {
        s2 = 0;
        int rem = local;
        while (s2 + 1 < Rb) {
            int cnt = J - 2*s2; if (cnt < 0) cnt = 0;
            if (rem < cnt) break;
            rem -= cnt; s2++;
        }
        tj = 2*s2 + rem;
    } else {
        s2 = local / J;
        tj = local - s2 * J;
    }

    __shared__ __align__(16) u64 sh[(TJ/2) * 8];
    float* shf = (float*)sh;

    const float4* A4 = (const float4*)A;
    const float4* B4 = (const float4*)B;

    int r0 = s2 * RPB + threadIdx.x;
    int r1 = r0 + TJ;
    u64 nR0[3], cR0[3], qR0, nR1[3], cR1[3], qR1;
    {
        float4 a0, a1;
        if (r0 < nRows) { a0 = A4[2*r0]; a1 = A4[2*r0+1]; }
        else { a0 = make_float4(0,0,0,0.5f); a1 = make_float4(0,0,0,0); }
        nR0[0]=pk2(a0.x,a0.x); nR0[1]=pk2(a0.y,a0.y); nR0[2]=pk2(a0.z,a0.z);
        cR0[0]=pk2(a1.x,a1.x); cR0[1]=pk2(a1.y,a1.y); cR0[2]=pk2(a1.z,a1.z);
        qR0 = pk2(a0.w,a0.w);
        if (r1 < nRows) { a0 = A4[2*r1]; a1 = A4[2*r1+1]; }
        else { a0 = make_float4(0,0,0,0.5f); a1 = make_float4(0,0,0,0); }
        nR1[0]=pk2(a0.x,a0.x); nR1[1]=pk2(a0.y,a0.y); nR1[2]=pk2(a0.z,a0.z);
        cR1[0]=pk2(a1.x,a1.x); cR1[1]=pk2(a1.y,a1.y); cR1[2]=pk2(a1.z,a1.z);
        qR1 = pk2(a0.w,a0.w);
    }

    // ---- shared fill (one tile) ----
    {
        int t = threadIdx.x;
        int j = tj * TJ + t;
        int p = t >> 1, h = t & 1;
        float nx, ny, nz, q, cx, cy, cz;
        if (j < nCols) {
            float4 b0 = B4[2*j];
            float4 b1 = B4[2*j+1];
            nx = b0.x; ny = b0.y; nz = b0.z; q = b0.w;
            cx = -2.0f*b1.x; cy = -2.0f*b1.y; cz = -2.0f*b1.z;
        } else {
            nx = ny = nz = 0.0f; q = 0.5f; cx = cy = cz = 0.0f;
        }
        float* d = shf + p*16 + h;
        d[0] = nx; d[2] = ny; d[4] = nz; d[6] = q;
        d[8] = cx; d[10] = cy; d[12] = cz;
    }
    __syncthreads();

    u64 aT0 = 0ull, aT1 = 0ull;
    const ulonglong2* shv = (const ulonglong2*)sh;
    #pragma unroll 4
    for (int p = 0; p < TJ/2; ++p) {
        ulonglong2 v0 = shv[p*4 + 0];   // nx2 ny2
        ulonglong2 v1 = shv[p*4 + 1];   // nz2 q2
        ulonglong2 v2 = shv[p*4 + 2];   // csx2 csy2
        ulonglong2 v3 = shv[p*4 + 3];   // csz2 pad

        {   // row 0
            u64 nn, u, rr;
            F2MUL(nn, nR0[0], v0.x);
            F2FMA(nn, nR0[1], v0.y, nn);
            F2FMA(nn, nR0[2], v1.x, nn);
            F2FMA(u, cR0[0], v2.x, v1.y);
            F2FMA(u, cR0[1], v2.y, u);
            F2FMA(u, cR0[2], v3.x, u);
            F2ADD(u, u, qR0);
            float ua, ub; upk2(ua, ub, u);
            u64 r2 = pk2(frcp(ua), frcp(ub));
            F2MUL(rr, r2, r2);
            F2FMA(aT0, nn, rr, aT0);
        }
        {   // row 1
            u64 nn, u, rr;
            F2MUL(nn, nR1[0], v0.x);
            F2FMA(nn, nR1[1], v0.y, nn);
            F2FMA(nn, nR1[2], v1.x, nn);
            F2FMA(u, cR1[0], v2.x, v1.y);
            F2FMA(u, cR1[1], v2.y, u);
            F2FMA(u, cR1[2], v3.x, u);
            F2ADD(u, u, qR1);
            float ua, ub; upk2(ua, ub, u);
            u64 r2 = pk2(frcp(ua), frcp(ub));
            F2MUL(rr, r2, r2);
            F2FMA(aT1, nn, rr, aT1);
        }
    }

    float w0f = 1.0f, w1f = 1.0f;
    if (sym) {
        int s0 = 2*s2, s1 = s0 + 1;
        w0f = (tj == s0) ? 1.0f : 2.0f;                       // tj >= s0 by decode
        w1f = (tj < s1) ? 0.0f : ((tj == s1) ? 1.0f : 2.0f);
    }

    float a_, b_, c_, d_;
    upk2(a_, b_, aT0); upk2(c_, d_, aT1);
    float acc = w * (w0f * (a_ + b_) + w1f * (c_ + d_));

    #pragma unroll
    for (int o = 16; o; o >>= 1)
        acc += __shfl_xor_sync(0xffffffffu, acc, o);

    __shared__ float wsum[NWARP];
    int wid = threadIdx.x >> 5;
    if ((threadIdx.x & 31) == 0) wsum[wid] = acc;
    __syncthreads();
    if (threadIdx.x == 0) {
        float s = 0.0f;
        #pragma unroll
        for (int k = 0; k < NWARP; k++) s += wsum[k];
        atomicAdd(&g_acc, (double)s);
        __threadfence();
        unsigned int ticket = atomicAdd(&g_done, 1u);
        if (ticket == (unsigned int)total - 1u) outp[0] = (float)g_acc;
    }
}

// ---------------------------------------------------------------------------
static inline int units_sym(int n) {
    int Rb = (n + RPB - 1) / RPB;
    int J  = (n + TJ - 1) / TJ;
    int u = 0;
    for (int s2 = 0; s2 < Rb; ++s2) { int c = J - 2*s2; if (c < 0) c = 0; u += c; }
    return u;
}
static inline int units_full(int nr, int nc) {
    return ((nr + RPB - 1) / RPB) * ((nc + TJ - 1) / TJ);
}

extern "C" void kernel_launch(void* const* d_in, const int* in_sizes, int n_in,
                              void* d_out, int out_size) {
    const float* sv = (const float*)d_in[0];
    const void*  si = d_in[1];
    const float* tv = (const float*)d_in[2];
    const void*  ti = d_in[3];
    const float* rn = (const float*)d_in[4];
    const float* rc = (const float*)d_in[5];

    int VSn = in_sizes[0] / 3;
    int FSn = in_sizes[1] / 3;
    int VTn = in_sizes[2] / 3;
    int FTn = in_sizes[3] / 3;
    int FRn = in_sizes[4] / 3;

    int nMax = FSn > FTn ? FSn : FTn;
    if (FRn > nMax) nMax = FRn;

    dim3 pgrid((nMax + 255) / 256, 3, 1);
    k_prep<<<pgrid, 256>>>(sv, si, VSn, FSn, tv, ti, VTn, FTn, rn, rc, FRn);

    int u0 = units_sym(FSn);          // ss
    int u1 = units_sym(FTn);          // tt
    int u2 = units_sym(FRn);          // rr
    int u3 = units_full(FRn, FSn);    // rs
    int u4 = units_full(FRn, FTn);    // rt
    int u5 = units_full(FTn, FSn);    // ts

    int o1 = u0;
    int o2 = o1 + u1;
    int o3 = o2 + u2;
    int o4 = o3 + u3;
    int o5 = o4 + u4;
    int total = o5 + u5;

    k_pair<<<total, NT>>>(FSn, FTn, FRn, o1, o2, o3, o4, o5, total, (float*)d_out);
}